// round 1
// baseline (speedup 1.0000x reference)
#include <cuda_runtime.h>
#include <cuda_bf16.h>
#include <mma.h>

using namespace nvcuda;

#define NB   1024
#define NK   16
#define NG   2000
#define ND   4000
#define NH   256
#define NR   16384
#define NRT  32768
#define OUTW 4256

// ------------------------- scratch (static device globals) -------------------
__device__ float g_C[NRT * NH];        // attention hidden pre-activation (33.5MB)
__device__ float g_att[NRT];           // attention logits
__device__ float g_w[2 * NB * NK];     // normalized weights
__device__ float g_wsum[2 * NB];       // sum of normalized weights (~1)
__device__ float g_agg[2][NB * ND];    // weighted neighbor aggregate (32.8MB)
__device__ float g_diff[NB * ND];      // agg1 - wsum*enc (16.4MB)
__device__ float g_h1[4][NB * NH];     // raw GEMM outs: agg1@W1, agg2@W1, diff@Wd, enc@Wr
__device__ int   g_rowidx[NRT];        // flattened gather indices

// ------------------------- row index flattening ------------------------------
__global__ void k_rowidx(const int* __restrict__ ni, const int* __restrict__ ni2) {
    int r = blockIdx.x * blockDim.x + threadIdx.x;
    if (r >= NRT) return;
    int g = r >> 14;
    int rem = r & (NR - 1);           // = b*NK + k
    g_rowidx[r] = (g ? ni2 : ni)[rem];
}

// ------------------------- attention GEMM (fused gather+log, TF32 wmma) ------
// C[32768,256] = log(0.01+gather)[32768,4000] @ Wa1[4000,256]
// CTA tile 128x256, 16 warps (4x4), warp tile 32x64, k-step 16.
__global__ __launch_bounds__(512) void k_attgemm(
    const float* __restrict__ sp, const float* __restrict__ un,
    const float* __restrict__ Wa1)
{
    __shared__ float sA[128 * 20];
    __shared__ float sB[16 * 264];
    const int tid  = threadIdx.x;
    const int warp = tid >> 5;
    const int wr   = warp >> 2;        // warp row block 0..3
    const int wc   = warp & 3;         // warp col block 0..3
    const int r0   = blockIdx.x * 128;

    const int arow = tid >> 2;         // 0..127
    const int aq   = (tid & 3) * 4;    // 0,4,8,12
    const int idx  = g_rowidx[r0 + arow];
    const float* rowsp = sp + (long)idx * NG;
    const float* rowun = un + (long)idx * NG;

    wmma::fragment<wmma::accumulator, 16, 16, 8, float> c[2][4];
#pragma unroll
    for (int i = 0; i < 2; i++)
#pragma unroll
        for (int j = 0; j < 4; j++) wmma::fill_fragment(c[i][j], 0.0f);

    for (int kk = 0; kk < ND; kk += 16) {
        // A tile: 128 rows x 16 cols, generated on the fly (gather + log + tf32 round)
        const float* src = (kk < NG) ? (rowsp + kk + aq) : (rowun + (kk - NG) + aq);
        float4 v = *(const float4*)src;
        float* da = &sA[arow * 20 + aq];
        da[0] = wmma::__float_to_tf32(__logf(0.01f + v.x));
        da[1] = wmma::__float_to_tf32(__logf(0.01f + v.y));
        da[2] = wmma::__float_to_tf32(__logf(0.01f + v.z));
        da[3] = wmma::__float_to_tf32(__logf(0.01f + v.w));
        // B tile: Wa1[kk:kk+16, 0:256]
        int lin = tid;
#pragma unroll
        for (int rep = 0; rep < 2; rep++) {
            int row = lin >> 6, c4 = (lin & 63) * 4;
            float4 bv = *(const float4*)(Wa1 + (kk + row) * NH + c4);
            float* db = &sB[row * 264 + c4];
            db[0] = wmma::__float_to_tf32(bv.x);
            db[1] = wmma::__float_to_tf32(bv.y);
            db[2] = wmma::__float_to_tf32(bv.z);
            db[3] = wmma::__float_to_tf32(bv.w);
            lin += 512;
        }
        __syncthreads();
#pragma unroll
        for (int ks = 0; ks < 16; ks += 8) {
            wmma::fragment<wmma::matrix_a, 16, 16, 8, wmma::precision::tf32, wmma::row_major> a[2];
            wmma::fragment<wmma::matrix_b, 16, 16, 8, wmma::precision::tf32, wmma::row_major> b[4];
#pragma unroll
            for (int i = 0; i < 2; i++)
                wmma::load_matrix_sync(a[i], &sA[(wr * 32 + i * 16) * 20 + ks], 20);
#pragma unroll
            for (int j = 0; j < 4; j++)
                wmma::load_matrix_sync(b[j], &sB[ks * 264 + wc * 64 + j * 16], 264);
#pragma unroll
            for (int i = 0; i < 2; i++)
#pragma unroll
                for (int j = 0; j < 4; j++)
                    wmma::mma_sync(c[i][j], a[i], b[j], c[i][j]);
        }
        __syncthreads();
    }
#pragma unroll
    for (int i = 0; i < 2; i++)
#pragma unroll
        for (int j = 0; j < 4; j++)
            wmma::store_matrix_sync(&g_C[(r0 + wr * 32 + i * 16) * NH + wc * 64 + j * 16],
                                    c[i][j], NH, wmma::mem_row_major);
}

// ------------------------- tanh + Wa2 reduction ------------------------------
__global__ void k_tanhred(const float* __restrict__ ba1, const float* __restrict__ Wa2,
                          const float* __restrict__ ba2) {
    int r = blockIdx.x * 8 + (threadIdx.x >> 5);
    int lane = threadIdx.x & 31;
    float s = 0.0f;
#pragma unroll
    for (int i = 0; i < 8; i++) {
        int n = lane + 32 * i;
        s += tanhf(g_C[r * NH + n] + ba1[n]) * Wa2[n];
    }
#pragma unroll
    for (int o = 16; o; o >>= 1) s += __shfl_down_sync(0xffffffffu, s, o);
    if (lane == 0) g_att[r] = s + ba2[0];
}

// ------------------------- softmax + weight normalize ------------------------
__global__ void k_softmax(const float* __restrict__ nw, const float* __restrict__ nw2) {
    int t = blockIdx.x * blockDim.x + threadIdx.x;
    if (t >= 2 * NB) return;
    int g = t >> 10, b = t & 1023;
    const float* nwp = (g ? nw2 : nw) + b * NK;
    const float* a = g_att + g * NR + b * NK;
    float m = -1e30f;
#pragma unroll
    for (int k = 0; k < NK; k++) m = fmaxf(m, a[k]);
    float e[NK], s = 0.0f;
#pragma unroll
    for (int k = 0; k < NK; k++) { e[k] = __expf(a[k] - m); s += e[k]; }
    float inv_s = 1.0f / s;
    float w[NK], ws = 0.0f;
#pragma unroll
    for (int k = 0; k < NK; k++) { w[k] = nwp[k] * e[k] * inv_s; ws += w[k]; }
    float inv = 1.0f / (ws + 1e-12f);
    float tot = 0.0f;
#pragma unroll
    for (int k = 0; k < NK; k++) { float v = w[k] * inv; g_w[t * NK + k] = v; tot += v; }
    g_wsum[t] = tot;
}

// ------------------------- weighted aggregation (fused gather+log) -----------
__global__ __launch_bounds__(256) void k_agg(const float* __restrict__ sp,
                                             const float* __restrict__ un,
                                             const float* __restrict__ enc) {
    int cta = blockIdx.x;              // 0..2047
    int g = cta >> 10, b = cta & 1023;
    __shared__ float ws[NK];
    __shared__ int   is[NK];
    __shared__ float s_wsum;
    if (threadIdx.x < NK) {
        ws[threadIdx.x] = g_w[cta * NK + threadIdx.x];
        is[threadIdx.x] = g_rowidx[g * NR + b * NK + threadIdx.x];
    }
    if (threadIdx.x == 0) s_wsum = g_wsum[cta];
    __syncthreads();
    float* aggp = g_agg[g] + b * ND;
    for (int q = threadIdx.x; q < 1000; q += 256) {
        int j = q * 4;
        const float* base; int col;
        if (j < NG) { base = sp; col = j; } else { base = un; col = j - NG; }
        float4 acc = make_float4(0.f, 0.f, 0.f, 0.f);
#pragma unroll
        for (int k = 0; k < NK; k++) {
            float4 v = *(const float4*)(base + (long)is[k] * NG + col);
            float wk = ws[k];
            acc.x += wk * __logf(0.01f + v.x);
            acc.y += wk * __logf(0.01f + v.y);
            acc.z += wk * __logf(0.01f + v.z);
            acc.w += wk * __logf(0.01f + v.w);
        }
        *(float4*)(aggp + j) = acc;
        if (g == 0) {
            float4 ev = *(const float4*)(enc + b * ND + j);
            float4 dv = make_float4(acc.x - s_wsum * ev.x, acc.y - s_wsum * ev.y,
                                    acc.z - s_wsum * ev.z, acc.w - s_wsum * ev.w);
            *(float4*)(g_diff + b * ND + j) = dv;
        }
    }
}

// ------------------------- projection GEMMs (4 segments, TF32 wmma) ----------
// out[seg][1024,256] = A_seg[1024,4000] @ W_seg[4000,256]   (raw, bias/relu later)
__global__ __launch_bounds__(256) void k_projgemm(const float* __restrict__ enc,
                                                  const float* __restrict__ W1,
                                                  const float* __restrict__ Wd,
                                                  const float* __restrict__ Wr) {
    const int seg = blockIdx.y;
    const float* Ap; const float* Wp;
    if      (seg == 0) { Ap = g_agg[0]; Wp = W1; }
    else if (seg == 1) { Ap = g_agg[1]; Wp = W1; }
    else if (seg == 2) { Ap = g_diff;   Wp = Wd; }
    else               { Ap = enc;      Wp = Wr; }

    __shared__ float sA[32 * 20];
    __shared__ float sB[16 * 264];
    const int tid  = threadIdx.x;
    const int warp = tid >> 5;         // col block 0..7 (32 cols each)
    const int r0   = blockIdx.x * 32;

    wmma::fragment<wmma::accumulator, 16, 16, 8, float> c[2][2];
#pragma unroll
    for (int i = 0; i < 2; i++)
#pragma unroll
        for (int j = 0; j < 2; j++) wmma::fill_fragment(c[i][j], 0.0f);

    for (int kk = 0; kk < ND; kk += 16) {
        if (tid < 128) {
            int row = tid >> 2, q = (tid & 3) * 4;
            float4 v = *(const float4*)(Ap + (long)(r0 + row) * ND + kk + q);
            float* da = &sA[row * 20 + q];
            da[0] = wmma::__float_to_tf32(v.x);
            da[1] = wmma::__float_to_tf32(v.y);
            da[2] = wmma::__float_to_tf32(v.z);
            da[3] = wmma::__float_to_tf32(v.w);
        }
        int lin = tid;
#pragma unroll
        for (int rep = 0; rep < 4; rep++) {
            int row = lin >> 6, c4 = (lin & 63) * 4;
            float4 bv = *(const float4*)(Wp + (kk + row) * NH + c4);
            float* db = &sB[row * 264 + c4];
            db[0] = wmma::__float_to_tf32(bv.x);
            db[1] = wmma::__float_to_tf32(bv.y);
            db[2] = wmma::__float_to_tf32(bv.z);
            db[3] = wmma::__float_to_tf32(bv.w);
            lin += 256;
        }
        __syncthreads();
#pragma unroll
        for (int ks = 0; ks < 16; ks += 8) {
            wmma::fragment<wmma::matrix_a, 16, 16, 8, wmma::precision::tf32, wmma::row_major> a[2];
            wmma::fragment<wmma::matrix_b, 16, 16, 8, wmma::precision::tf32, wmma::row_major> b[2];
#pragma unroll
            for (int i = 0; i < 2; i++)
                wmma::load_matrix_sync(a[i], &sA[(i * 16) * 20 + ks], 20);
#pragma unroll
            for (int j = 0; j < 2; j++)
                wmma::load_matrix_sync(b[j], &sB[ks * 264 + warp * 32 + j * 16], 264);
#pragma unroll
            for (int i = 0; i < 2; i++)
#pragma unroll
                for (int j = 0; j < 2; j++)
                    wmma::mma_sync(c[i][j], a[i], b[j], c[i][j]);
        }
        __syncthreads();
    }
#pragma unroll
    for (int i = 0; i < 2; i++)
#pragma unroll
        for (int j = 0; j < 2; j++)
            wmma::store_matrix_sync(&g_h1[seg][(r0 + i * 16) * NH + warp * 32 + j * 16],
                                    c[i][j], NH, wmma::mem_row_major);
}

// ------------------------- final: layer2, gates, LN, output ------------------
__global__ __launch_bounds__(256) void k_final(
    const float* __restrict__ W2, const float* __restrict__ b1, const float* __restrict__ b2,
    const float* __restrict__ bd, const float* __restrict__ br,
    const float* __restrict__ gamma, const float* __restrict__ beta,
    const float* __restrict__ mg, const float* __restrict__ cgg,
    float* __restrict__ out)
{
    int b = blockIdx.x, n = threadIdx.x;
    __shared__ float h1a[NH], h1b[NH];
    h1a[n] = fmaxf(g_h1[0][b * NH + n] + b1[n], 0.0f);
    h1b[n] = fmaxf(g_h1[1][b * NH + n] + b1[n], 0.0f);
    __syncthreads();
    float aa = b2[n], ab = b2[n];
#pragma unroll 8
    for (int m = 0; m < NH; m++) {
        float w = W2[m * NH + n];
        aa += h1a[m] * w;
        ab += h1b[m] * w;
    }
    float h2a = fmaxf(aa, 0.0f), h2b = fmaxf(ab, 0.0f);
    float gcg = 1.0f / (1.0f + __expf(-cgg[n]));
    float p = gcg * h2a + (1.0f - gcg) * h2b;
    p += fmaxf(g_h1[2][b * NH + n] + bd[n], 0.0f);
    p += fmaxf(g_h1[3][b * NH + n] + br[n], 0.0f);
    // LayerNorm over 256
    __shared__ float red[16];
    float s1 = p, s2 = p * p;
#pragma unroll
    for (int o = 16; o; o >>= 1) {
        s1 += __shfl_down_sync(0xffffffffu, s1, o);
        s2 += __shfl_down_sync(0xffffffffu, s2, o);
    }
    int lane = n & 31, wid = n >> 5;
    if (lane == 0) { red[wid] = s1; red[8 + wid] = s2; }
    __syncthreads();
    if (n == 0) {
        float t1 = 0.f, t2 = 0.f;
        for (int i = 0; i < 8; i++) { t1 += red[i]; t2 += red[8 + i]; }
        red[0] = t1; red[8] = t2;
    }
    __syncthreads();
    float mu = red[0] * (1.0f / NH);
    float var = red[8] * (1.0f / NH) - mu * mu;
    float y = (p - mu) * rsqrtf(var + 1e-5f) * gamma[n] + beta[n];
    float mgs = 1.0f / (1.0f + __expf(-mg[n]));
    out[(long)b * OUTW + ND + n] = mgs * y;
}

// ------------------------- copy encoder_input into output --------------------
__global__ void k_copy(const float* __restrict__ enc, float* __restrict__ out) {
    long t = (long)blockIdx.x * blockDim.x + threadIdx.x;
    if (t >= (long)NB * 1000) return;
    int b = (int)(t / 1000), q = (int)(t % 1000);
    float4 v = *(const float4*)(enc + (long)b * ND + q * 4);
    *(float4*)(out + (long)b * OUTW + q * 4) = v;
}

// ------------------------- launch ---------------------------------------------
extern "C" void kernel_launch(void* const* d_in, const int* in_sizes, int n_in,
                              void* d_out, int out_size) {
    const float* enc = (const float*)d_in[0];
    const int*   ni  = (const int*)d_in[1];
    const float* nw  = (const float*)d_in[2];
    const int*   ni2 = (const int*)d_in[3];
    const float* nw2 = (const float*)d_in[4];
    const float* sp  = (const float*)d_in[5];
    const float* un  = (const float*)d_in[6];
    const float* W1  = (const float*)d_in[7];
    const float* b1  = (const float*)d_in[8];
    const float* W2  = (const float*)d_in[9];
    const float* b2  = (const float*)d_in[10];
    const float* Wa1 = (const float*)d_in[11];
    const float* ba1 = (const float*)d_in[12];
    const float* Wa2 = (const float*)d_in[13];
    const float* ba2 = (const float*)d_in[14];
    const float* Wd  = (const float*)d_in[15];
    const float* bd  = (const float*)d_in[16];
    const float* Wr  = (const float*)d_in[17];
    const float* br  = (const float*)d_in[18];
    const float* gamma = (const float*)d_in[19];
    const float* beta  = (const float*)d_in[20];
    const float* mg    = (const float*)d_in[21];
    const float* cgg   = (const float*)d_in[22];
    float* out = (float*)d_out;

    k_rowidx<<<NRT / 256, 256>>>(ni, ni2);
    k_copy<<<4000, 256>>>(enc, out);
    k_attgemm<<<NRT / 128, 512>>>(sp, un, Wa1);
    k_tanhred<<<NRT / 8, 256>>>(ba1, Wa2, ba2);
    k_softmax<<<8, 256>>>(nw, nw2);
    k_agg<<<2 * NB, 256>>>(sp, un, enc);
    k_projgemm<<<dim3(NB / 32, 4), 256>>>(enc, W1, Wd, Wr);
    k_final<<<NB, 256>>>(W2, b1, b2, bd, br, gamma, beta, mg, cgg, out);
}

// round 3
// speedup vs baseline: 2.6988x; 2.6988x over previous
#include <cuda_runtime.h>
#include <cuda_bf16.h>
#include <mma.h>
#include <cstdint>

using namespace nvcuda;
typedef __nv_bfloat16 bf16;

#define NB   1024
#define NK   16
#define NG   2000
#define ND   4000
#define NH   256
#define NR   16384
#define NRT  32768
#define OUTW 4256

// ------------------------- scratch (static device globals) -------------------
__device__ bf16  g_nfb[(long)NRT * ND];   // log-features, bf16 (250MB)
__device__ float g_C[NRT * NH];           // attention hidden pre-activation
__device__ float g_att[NRT];
__device__ float g_w[2 * NB * NK];
__device__ float g_wsum[2 * NB];
__device__ bf16  g_aggb[2][NB * ND];      // weighted aggregates, bf16
__device__ bf16  g_diffb[NB * ND];
__device__ bf16  g_encb[NB * ND];
__device__ bf16  g_Wa1b[ND * NH];
__device__ bf16  g_W1b[ND * NH];
__device__ bf16  g_Wdb[ND * NH];
__device__ bf16  g_Wrb[ND * NH];
__device__ float g_h1[4][NB * NH];
__device__ int   g_rowidx[NRT];

// ------------------------- tiny helpers --------------------------------------
__device__ __forceinline__ void cp16(void* smem, const void* gmem) {
    unsigned int s = (unsigned int)__cvta_generic_to_shared(smem);
    asm volatile("cp.async.cg.shared.global [%0], [%1], 16;" :: "r"(s), "l"(gmem));
}

__global__ void k_rowidx(const int* __restrict__ ni, const int* __restrict__ ni2) {
    int r = blockIdx.x * blockDim.x + threadIdx.x;
    if (r >= NRT) return;
    int g = r >> 14;
    g_rowidx[r] = (g ? ni2 : ni)[r & (NR - 1)];
}

__global__ void k_f2bf(const float* __restrict__ src, bf16* __restrict__ dst, int n4) {
    int t = blockIdx.x * blockDim.x + threadIdx.x;
    if (t >= n4) return;
    float4 v = *(const float4*)(src + t * 4);
    bf16 o[4] = { __float2bfloat16(v.x), __float2bfloat16(v.y),
                  __float2bfloat16(v.z), __float2bfloat16(v.w) };
    *(uint2*)(dst + t * 4) = *(uint2*)o;
}

// ------------------------- gather + log -> bf16 -------------------------------
__global__ __launch_bounds__(128) void k_gatherlog(const float* __restrict__ sp,
                                                   const float* __restrict__ un) {
    int r = blockIdx.x;
    int idx = g_rowidx[r];
    const float* rs = sp + (long)idx * NG;
    const float* ru = un + (long)idx * NG;
    bf16* dst = g_nfb + (long)r * ND;
    for (int p = threadIdx.x; p < 500; p += 128) {
        const float* src = (p < 250) ? (rs + p * 8) : (ru + (p - 250) * 8);
        float4 a = *(const float4*)src;
        float4 b = *(const float4*)(src + 4);
        bf16 o[8];
        o[0] = __float2bfloat16(__logf(0.01f + a.x));
        o[1] = __float2bfloat16(__logf(0.01f + a.y));
        o[2] = __float2bfloat16(__logf(0.01f + a.z));
        o[3] = __float2bfloat16(__logf(0.01f + a.w));
        o[4] = __float2bfloat16(__logf(0.01f + b.x));
        o[5] = __float2bfloat16(__logf(0.01f + b.y));
        o[6] = __float2bfloat16(__logf(0.01f + b.z));
        o[7] = __float2bfloat16(__logf(0.01f + b.w));
        *(int4*)(dst + p * 8) = *(int4*)o;
    }
}

// ------------------------- bf16 GEMM body: C[128,256] += A[128,4000]@B[4000,256]
// 256 threads, 8 warps (2x4), warp tile 64x64, k-tile 32, 2-stage cp.async.
#define SA_STRIDE 40
#define SB_STRIDE 264
#define SA_ELEMS (128 * SA_STRIDE)
#define SB_ELEMS (32 * SB_STRIDE)
#define GEMM_SMEM ((2 * SA_ELEMS + 2 * SB_ELEMS) * 2)

__device__ __forceinline__ void gemm_body(const bf16* __restrict__ A,
                                          const bf16* __restrict__ Bw,
                                          float* __restrict__ C, int r0,
                                          bf16* smem) {
    const int tid  = threadIdx.x;
    const int warp = tid >> 5;
    const int wr   = warp >> 2;
    const int wc   = warp & 3;
    bf16* sA[2] = { smem, smem + SA_ELEMS };
    bf16* sB[2] = { smem + 2 * SA_ELEMS, smem + 2 * SA_ELEMS + SB_ELEMS };

    wmma::fragment<wmma::accumulator, 16, 16, 16, float> c[4][4];
#pragma unroll
    for (int i = 0; i < 4; i++)
#pragma unroll
        for (int j = 0; j < 4; j++) wmma::fill_fragment(c[i][j], 0.0f);

    auto load_tile = [&](int it, int s) {
        int kk = it * 32;
#pragma unroll
        for (int c0 = 0; c0 < 2; c0++) {
            int ch = tid + c0 * 256;
            int row = ch >> 2, q = ch & 3;
            cp16(sA[s] + row * SA_STRIDE + q * 8,
                 A + (long)(r0 + row) * ND + kk + q * 8);
        }
#pragma unroll
        for (int c0 = 0; c0 < 4; c0++) {
            int ch = tid + c0 * 256;
            int row = ch >> 5, q = ch & 31;
            cp16(sB[s] + row * SB_STRIDE + q * 8,
                 Bw + (long)(kk + row) * NH + q * 8);
        }
        asm volatile("cp.async.commit_group;");
    };

    load_tile(0, 0);
    for (int it = 0; it < ND / 32; it++) {
        int s = it & 1;
        if (it + 1 < ND / 32) {
            load_tile(it + 1, s ^ 1);
            asm volatile("cp.async.wait_group 1;");
        } else {
            asm volatile("cp.async.wait_group 0;");
        }
        __syncthreads();
#pragma unroll
        for (int ks = 0; ks < 32; ks += 16) {
            wmma::fragment<wmma::matrix_a, 16, 16, 16, bf16, wmma::row_major> af[4];
            wmma::fragment<wmma::matrix_b, 16, 16, 16, bf16, wmma::row_major> bfr[4];
#pragma unroll
            for (int i = 0; i < 4; i++)
                wmma::load_matrix_sync(af[i], sA[s] + (wr * 64 + i * 16) * SA_STRIDE + ks, SA_STRIDE);
#pragma unroll
            for (int j = 0; j < 4; j++)
                wmma::load_matrix_sync(bfr[j], sB[s] + ks * SB_STRIDE + wc * 64 + j * 16, SB_STRIDE);
#pragma unroll
            for (int i = 0; i < 4; i++)
#pragma unroll
                for (int j = 0; j < 4; j++)
                    wmma::mma_sync(c[i][j], af[i], bfr[j], c[i][j]);
        }
        __syncthreads();
    }
#pragma unroll
    for (int i = 0; i < 4; i++)
#pragma unroll
        for (int j = 0; j < 4; j++)
            wmma::store_matrix_sync(&C[(long)(r0 + wr * 64 + i * 16) * NH + wc * 64 + j * 16],
                                    c[i][j], NH, wmma::mem_row_major);
}

__global__ __launch_bounds__(256, 1) void k_gemm_att() {
    extern __shared__ bf16 smem[];
    gemm_body(g_nfb, g_Wa1b, g_C, blockIdx.x * 128, smem);
}

__global__ __launch_bounds__(256, 1) void k_gemm_proj() {
    extern __shared__ bf16 smem[];
    int seg = blockIdx.y;
    const bf16* A = (seg == 0) ? g_aggb[0] : (seg == 1) ? g_aggb[1]
                  : (seg == 2) ? g_diffb : g_encb;
    const bf16* B = (seg < 2) ? g_W1b : (seg == 2) ? g_Wdb : g_Wrb;
    gemm_body(A, B, g_h1[seg], blockIdx.x * 128, smem);
}

// ------------------------- tanh + Wa2 reduction ------------------------------
__global__ void k_tanhred(const float* __restrict__ ba1, const float* __restrict__ Wa2,
                          const float* __restrict__ ba2) {
    int r = blockIdx.x * 8 + (threadIdx.x >> 5);
    int lane = threadIdx.x & 31;
    float s = 0.0f;
#pragma unroll
    for (int i = 0; i < 8; i++) {
        int n = lane + 32 * i;
        s += tanhf(g_C[r * NH + n] + ba1[n]) * Wa2[n];
    }
#pragma unroll
    for (int o = 16; o; o >>= 1) s += __shfl_down_sync(0xffffffffu, s, o);
    if (lane == 0) g_att[r] = s + ba2[0];
}

// ------------------------- softmax + weight normalize ------------------------
__global__ void k_softmax(const float* __restrict__ nw, const float* __restrict__ nw2) {
    int t = blockIdx.x * blockDim.x + threadIdx.x;
    if (t >= 2 * NB) return;
    int g = t >> 10, b = t & 1023;
    const float* nwp = (g ? nw2 : nw) + b * NK;
    const float* a = g_att + g * NR + b * NK;
    float m = -1e30f;
#pragma unroll
    for (int k = 0; k < NK; k++) m = fmaxf(m, a[k]);
    float e[NK], s = 0.0f;
#pragma unroll
    for (int k = 0; k < NK; k++) { e[k] = __expf(a[k] - m); s += e[k]; }
    float inv_s = 1.0f / s;
    float w[NK], ws = 0.0f;
#pragma unroll
    for (int k = 0; k < NK; k++) { w[k] = nwp[k] * e[k] * inv_s; ws += w[k]; }
    float inv = 1.0f / (ws + 1e-12f);
    float tot = 0.0f;
#pragma unroll
    for (int k = 0; k < NK; k++) { float v = w[k] * inv; g_w[t * NK + k] = v; tot += v; }
    g_wsum[t] = tot;
}

// ------------------------- weighted aggregation (reads nfb) ------------------
__global__ __launch_bounds__(256) void k_agg(const float* __restrict__ enc) {
    int cta = blockIdx.x;              // 0..2047
    int g = cta >> 10, b = cta & 1023;
    __shared__ float ws[NK];
    __shared__ float s_wsum;
    if (threadIdx.x < NK) ws[threadIdx.x] = g_w[cta * NK + threadIdx.x];
    if (threadIdx.x == 0) s_wsum = g_wsum[cta];
    __syncthreads();
    const bf16* base = g_nfb + (long)(g * NR + b * NK) * ND;
    for (int p = threadIdx.x; p < 500; p += 256) {
        float acc[8] = {0, 0, 0, 0, 0, 0, 0, 0};
#pragma unroll
        for (int k = 0; k < NK; k++) {
            int4 v = *(const int4*)(base + (long)k * ND + p * 8);
            const __nv_bfloat162* h = (const __nv_bfloat162*)&v;
            float wk = ws[k];
#pragma unroll
            for (int q = 0; q < 4; q++) {
                float2 f = __bfloat1622float2(h[q]);
                acc[2 * q]     += wk * f.x;
                acc[2 * q + 1] += wk * f.y;
            }
        }
        bf16 oa[8];
#pragma unroll
        for (int q = 0; q < 8; q++) oa[q] = __float2bfloat16(acc[q]);
        *(int4*)(g_aggb[g] + (long)b * ND + p * 8) = *(int4*)oa;
        if (g == 0) {
            float4 e0 = *(const float4*)(enc + (long)b * ND + p * 8);
            float4 e1 = *(const float4*)(enc + (long)b * ND + p * 8 + 4);
            float ev[8] = { e0.x, e0.y, e0.z, e0.w, e1.x, e1.y, e1.z, e1.w };
            bf16 od[8];
#pragma unroll
            for (int q = 0; q < 8; q++) od[q] = __float2bfloat16(acc[q] - s_wsum * ev[q]);
            *(int4*)(g_diffb + (long)b * ND + p * 8) = *(int4*)od;
        }
    }
}

// ------------------------- final: layer2, gates, LN, output ------------------
__global__ __launch_bounds__(256) void k_final(
    const float* __restrict__ W2, const float* __restrict__ b1, const float* __restrict__ b2,
    const float* __restrict__ bd, const float* __restrict__ br,
    const float* __restrict__ gamma, const float* __restrict__ beta,
    const float* __restrict__ mg, const float* __restrict__ cgg,
    float* __restrict__ out)
{
    int b = blockIdx.x, n = threadIdx.x;
    __shared__ float h1a[NH], h1b[NH];
    h1a[n] = fmaxf(g_h1[0][b * NH + n] + b1[n], 0.0f);
    h1b[n] = fmaxf(g_h1[1][b * NH + n] + b1[n], 0.0f);
    __syncthreads();
    float aa = b2[n], ab = b2[n];
#pragma unroll 8
    for (int m = 0; m < NH; m++) {
        float w = W2[m * NH + n];
        aa += h1a[m] * w;
        ab += h1b[m] * w;
    }
    float h2a = fmaxf(aa, 0.0f), h2b = fmaxf(ab, 0.0f);
    float gcg = 1.0f / (1.0f + __expf(-cgg[n]));
    float p = gcg * h2a + (1.0f - gcg) * h2b;
    p += fmaxf(g_h1[2][b * NH + n] + bd[n], 0.0f);
    p += fmaxf(g_h1[3][b * NH + n] + br[n], 0.0f);
    __shared__ float red[16];
    float s1 = p, s2 = p * p;
#pragma unroll
    for (int o = 16; o; o >>= 1) {
        s1 += __shfl_down_sync(0xffffffffu, s1, o);
        s2 += __shfl_down_sync(0xffffffffu, s2, o);
    }
    int lane = n & 31, wid = n >> 5;
    if (lane == 0) { red[wid] = s1; red[8 + wid] = s2; }
    __syncthreads();
    if (n == 0) {
        float t1 = 0.f, t2 = 0.f;
        for (int i = 0; i < 8; i++) { t1 += red[i]; t2 += red[8 + i]; }
        red[0] = t1; red[8] = t2;
    }
    __syncthreads();
    float mu = red[0] * (1.0f / NH);
    float var = red[8] * (1.0f / NH) - mu * mu;
    float y = (p - mu) * rsqrtf(var + 1e-5f) * gamma[n] + beta[n];
    float mgs = 1.0f / (1.0f + __expf(-mg[n]));
    out[(long)b * OUTW + ND + n] = mgs * y;
}

// ------------------------- copy encoder_input into output --------------------
__global__ void k_copy(const float* __restrict__ enc, float* __restrict__ out) {
    long t = (long)blockIdx.x * blockDim.x + threadIdx.x;
    if (t >= (long)NB * 1000) return;
    int b = (int)(t / 1000), q = (int)(t % 1000);
    float4 v = *(const float4*)(enc + (long)b * ND + q * 4);
    *(float4*)(out + (long)b * OUTW + q * 4) = v;
}

// ------------------------- launch ---------------------------------------------
extern "C" void kernel_launch(void* const* d_in, const int* in_sizes, int n_in,
                              void* d_out, int out_size) {
    const float* enc = (const float*)d_in[0];
    const int*   ni  = (const int*)d_in[1];
    const float* nw  = (const float*)d_in[2];
    const int*   ni2 = (const int*)d_in[3];
    const float* nw2 = (const float*)d_in[4];
    const float* sp  = (const float*)d_in[5];
    const float* un  = (const float*)d_in[6];
    const float* W1  = (const float*)d_in[7];
    const float* b1  = (const float*)d_in[8];
    const float* W2  = (const float*)d_in[9];
    const float* b2  = (const float*)d_in[10];
    const float* Wa1 = (const float*)d_in[11];
    const float* ba1 = (const float*)d_in[12];
    const float* Wa2 = (const float*)d_in[13];
    const float* ba2 = (const float*)d_in[14];
    const float* Wd  = (const float*)d_in[15];
    const float* bd  = (const float*)d_in[16];
    const float* Wr  = (const float*)d_in[17];
    const float* br  = (const float*)d_in[18];
    const float* gamma = (const float*)d_in[19];
    const float* beta  = (const float*)d_in[20];
    const float* mg    = (const float*)d_in[21];
    const float* cgg   = (const float*)d_in[22];
    float* out = (float*)d_out;

    cudaFuncSetAttribute(k_gemm_att,  cudaFuncAttributeMaxDynamicSharedMemorySize, GEMM_SMEM);
    cudaFuncSetAttribute(k_gemm_proj, cudaFuncAttributeMaxDynamicSharedMemorySize, GEMM_SMEM);

    bf16 *wa1b, *w1b, *wdb, *wrb, *encb;
    cudaGetSymbolAddress((void**)&wa1b, g_Wa1b);
    cudaGetSymbolAddress((void**)&w1b,  g_W1b);
    cudaGetSymbolAddress((void**)&wdb,  g_Wdb);
    cudaGetSymbolAddress((void**)&wrb,  g_Wrb);
    cudaGetSymbolAddress((void**)&encb, g_encb);

    k_rowidx<<<NRT / 256, 256>>>(ni, ni2);
    k_f2bf<<<(ND * NH / 4 + 255) / 256, 256>>>(Wa1, wa1b, ND * NH / 4);
    k_f2bf<<<(ND * NH / 4 + 255) / 256, 256>>>(W1,  w1b,  ND * NH / 4);
    k_f2bf<<<(ND * NH / 4 + 255) / 256, 256>>>(Wd,  wdb,  ND * NH / 4);
    k_f2bf<<<(ND * NH / 4 + 255) / 256, 256>>>(Wr,  wrb,  ND * NH / 4);
    k_f2bf<<<(NB * ND / 4 + 255) / 256, 256>>>(enc, encb, NB * ND / 4);
    k_copy<<<4000, 256>>>(enc, out);
    k_gatherlog<<<NRT, 128>>>(sp, un);
    k_gemm_att<<<NRT / 128, 256, GEMM_SMEM>>>();
    k_tanhred<<<NRT / 8, 256>>>(ba1, Wa2, ba2);
    k_softmax<<<8, 256>>>(nw, nw2);
    k_agg<<<2 * NB, 256>>>(enc);
    k_gemm_proj<<<dim3(NB / 128, 4), 256, GEMM_SMEM>>>();
    k_final<<<NB, 256>>>(W2, b1, b2, bd, br, gamma, beta, mg, cgg, out);
}